// round 4
// baseline (speedup 1.0000x reference)
#include <cuda_runtime.h>
#include <cuda_bf16.h>
#include <mma.h>
#include <cstdint>

using namespace nvcuda;

#define B_ 2
#define S_ 4096
#define E_ 1024
#define H_ 16
#define D_ 64
#define NTOK (B_*S_)
#define NELEM (NTOK*E_)
#define KAUG 1056   // 1024 + 32 (bias row + zero pad), 33 tiles of BK=32

__device__ float g_q[NELEM];
__device__ float g_k[NELEM];
__device__ float g_v[NELEM];
__device__ float g_xc[NTOK * KAUG];        // tf32 X, augmented
__device__ float g_wc[3 * E_ * KAUG];      // tf32 W (scaled), augmented with bias

__device__ __forceinline__ void cp16(unsigned int dst, const void* src) {
    asm volatile("cp.async.cg.shared.global [%0], [%1], 16;" :: "r"(dst), "l"(src));
}
__device__ __forceinline__ unsigned int sptr(const void* p) {
    return (unsigned int)__cvta_generic_to_shared(p);
}

// ---------------------------------------------------------------------------
// One-time conversions to tf32 with K-augmentation.
// ---------------------------------------------------------------------------
__global__ void __launch_bounds__(256) cvt_x(const float* __restrict__ X) {
    int idx = blockIdx.x * 256 + threadIdx.x;
    if (idx >= NTOK * KAUG) return;
    int row = idx / KAUG, col = idx - row * KAUG;
    float v;
    if (col < 1024)       v = wmma::__float_to_tf32(X[(size_t)row * 1024 + col]);
    else if (col == 1024) v = 1.0f;
    else                  v = 0.0f;
    g_xc[idx] = v;
}

__global__ void __launch_bounds__(256) cvt_w(const float* __restrict__ w,
                                             const float* __restrict__ b,
                                             float scale, int which) {
    int idx = blockIdx.x * 256 + threadIdx.x;
    if (idx >= E_ * KAUG) return;
    int n = idx / KAUG, k = idx - n * KAUG;
    float v;
    if (k < 1024)       v = wmma::__float_to_tf32(w[(size_t)n * 1024 + k] * scale);
    else if (k == 1024) v = wmma::__float_to_tf32(b[n] * scale);
    else                v = 0.0f;
    g_wc[(size_t)which * E_ * KAUG + idx] = v;
}

// ---------------------------------------------------------------------------
// Projection GEMM: C = Xc @ Wc^T (bias folded). Double-buffered cp.async,
// BM=BN=128, BK=32, 256 threads, warp grid 2x4 (64x32 per warp).
// ---------------------------------------------------------------------------
#define GSTRIDE 36

__global__ void __launch_bounds__(256, 2) gemm_qkv() {
    __shared__ float As[2][128][GSTRIDE];
    __shared__ float Bs[2][128][GSTRIDE];

    const int which = blockIdx.z;
    const float* wbase = g_wc + (size_t)which * E_ * KAUG;
    float* C = (which == 0) ? g_q : ((which == 1) ? g_k : g_v);

    const int m0 = blockIdx.y * 128;
    const int n0 = blockIdx.x * 128;
    const int tid = threadIdx.x;
    const int warp = tid >> 5;
    const int wm = warp >> 2;    // 0..1 -> 64 rows
    const int wn = warp & 3;     // 0..3 -> 32 cols

    wmma::fragment<wmma::accumulator, 16, 16, 8, float> acc[4][2];
#pragma unroll
    for (int mm = 0; mm < 4; mm++)
#pragma unroll
        for (int nn = 0; nn < 2; nn++)
            wmma::fill_fragment(acc[mm][nn], 0.0f);

    auto issue = [&](int kt, int s) {
#pragma unroll
        for (int i = 0; i < 4; i++) {
            int c = tid + i * 256;
            int row = c >> 3, kc = (c & 7) * 4;
            cp16(sptr(&As[s][row][kc]), g_xc + (size_t)(m0 + row) * KAUG + kt * 32 + kc);
            cp16(sptr(&Bs[s][row][kc]), wbase + (size_t)(n0 + row) * KAUG + kt * 32 + kc);
        }
        asm volatile("cp.async.commit_group;" ::);
    };

    issue(0, 0);
    for (int kt = 0; kt < 33; kt++) {
        const int s = kt & 1;
        if (kt + 1 < 33) {
            issue(kt + 1, s ^ 1);
            asm volatile("cp.async.wait_group 1;" ::);
        } else {
            asm volatile("cp.async.wait_group 0;" ::);
        }
        __syncthreads();
#pragma unroll
        for (int ks = 0; ks < 4; ks++) {
            wmma::fragment<wmma::matrix_a, 16, 16, 8, wmma::precision::tf32, wmma::row_major> af[4];
            wmma::fragment<wmma::matrix_b, 16, 16, 8, wmma::precision::tf32, wmma::col_major> bf[2];
#pragma unroll
            for (int mm = 0; mm < 4; mm++)
                wmma::load_matrix_sync(af[mm], &As[s][wm * 64 + mm * 16][ks * 8], GSTRIDE);
#pragma unroll
            for (int nn = 0; nn < 2; nn++)
                wmma::load_matrix_sync(bf[nn], &Bs[s][wn * 32 + nn * 16][ks * 8], GSTRIDE);
#pragma unroll
            for (int mm = 0; mm < 4; mm++)
#pragma unroll
                for (int nn = 0; nn < 2; nn++)
                    wmma::mma_sync(acc[mm][nn], af[mm], bf[nn], acc[mm][nn]);
        }
        __syncthreads();
    }

    // Epilogue: round to tf32 (attention consumes these as MMA operands).
#pragma unroll
    for (int mm = 0; mm < 4; mm++)
#pragma unroll
        for (int nn = 0; nn < 2; nn++) {
#pragma unroll
            for (int e = 0; e < 8; e++)
                acc[mm][nn].x[e] = wmma::__float_to_tf32(acc[mm][nn].x[e]);
            wmma::store_matrix_sync(C + (size_t)(m0 + wm * 64 + mm * 16) * 1024
                                      + (n0 + wn * 32 + nn * 16),
                                    acc[mm][nn], 1024, wmma::mem_row_major);
        }
}

// ---------------------------------------------------------------------------
// Banded attention, WMMA tf32. One block = 128 queries x one (b,h).
// Band = 10 key tiles of 64 covering [chunk0-256, chunk0+128+256).
// No running max (scores O(1), masked -> exp underflow to 0); O stays in
// fragments across tiles; warp-level skip of fully-out-of-band corner tiles.
// ---------------------------------------------------------------------------
#define AP 72
#define ATTN_SMEM ((128*AP + 64*AP + 64*AP + 128*AP + 64 + 256) * 4)

__global__ void __launch_bounds__(256, 2) attn_wmma(const int* __restrict__ am,
                                                    float* __restrict__ out) {
    extern __shared__ float sm[];
    float* Qs = sm;                  // [128][AP]
    float* Ks = Qs + 128 * AP;       // [64][AP]
    float* Vs = Ks + 64 * AP;        // [64][AP]
    float* Ps = Vs + 64 * AP;        // [128][AP]
    float* fmS = Ps + 128 * AP;      // [64]
    float* lred = fmS + 64;          // [256]

    const int chunk0 = blockIdx.x * 128;
    const int h = blockIdx.y;
    const int b = blockIdx.z;
    const int tid = threadIdx.x;
    const int warp = tid >> 5;
    const int wm = warp >> 1;        // 0..3 -> 32 query rows
    const int wn = warp & 1;         // 0..1 -> 32 cols (keys for S, d for O)
    const int erow = tid >> 1;       // exp row 0..127
    const int ecoff = (tid & 1) * 32;

    const size_t base = (size_t)b * S_ * E_ + h * 64;

    // Load Q tile (already tf32-rounded by gemm epilogue)
#pragma unroll
    for (int r = 0; r < 8; r++) {
        int idx = tid + r * 256;
        int row = idx >> 4, c4 = idx & 15;
        float4 v = *(const float4*)(g_q + base + (size_t)(chunk0 + row) * E_ + c4 * 4);
        *(float4*)(&Qs[row * AP + c4 * 4]) = v;
    }

    wmma::fragment<wmma::accumulator, 16, 16, 8, float> oacc[2][2];
#pragma unroll
    for (int mm = 0; mm < 2; mm++)
#pragma unroll
        for (int nn = 0; nn < 2; nn++)
            wmma::fill_fragment(oacc[mm][nn], 0.0f);
    float lpart = 0.0f;

    for (int kt = 0; kt < 10; kt++) {
        const int kglob = chunk0 - 256 + kt * 64;
        if (kglob < 0 || kglob >= S_) continue;   // tiles fully in or out
        const int kofs = kt * 64 - 256;           // tile offset rel. to query base
        const bool wvalid = (kofs <= wm * 32 + 31 + 256) && (kofs + 63 >= wm * 32 - 256);

        __syncthreads();
#pragma unroll
        for (int r = 0; r < 4; r++) {
            int idx = tid + r * 256;
            int row = idx >> 4, c4 = idx & 15;
            size_t off = base + (size_t)(kglob + row) * E_ + c4 * 4;
            *(float4*)(&Ks[row * AP + c4 * 4]) = *(const float4*)(g_k + off);
            *(float4*)(&Vs[row * AP + c4 * 4]) = *(const float4*)(g_v + off);
        }
        if (tid < 64)
            fmS[tid] = (am[(size_t)b * S_ + kglob + tid] != 0) ? -10000.f : 0.f;
        __syncthreads();

        // S = Q @ K^T for this warp's 32x32 region
        if (wvalid) {
            wmma::fragment<wmma::accumulator, 16, 16, 8, float> sacc[2][2];
#pragma unroll
            for (int mm = 0; mm < 2; mm++)
#pragma unroll
                for (int nn = 0; nn < 2; nn++)
                    wmma::fill_fragment(sacc[mm][nn], 0.0f);
#pragma unroll
            for (int ks = 0; ks < 8; ks++) {
                wmma::fragment<wmma::matrix_a, 16, 16, 8, wmma::precision::tf32, wmma::row_major> af[2];
                wmma::fragment<wmma::matrix_b, 16, 16, 8, wmma::precision::tf32, wmma::col_major> bf[2];
#pragma unroll
                for (int mm = 0; mm < 2; mm++)
                    wmma::load_matrix_sync(af[mm], &Qs[(wm * 32 + mm * 16) * AP + ks * 8], AP);
#pragma unroll
                for (int nn = 0; nn < 2; nn++)
                    wmma::load_matrix_sync(bf[nn], &Ks[(wn * 32 + nn * 16) * AP + ks * 8], AP);
#pragma unroll
                for (int mm = 0; mm < 2; mm++)
#pragma unroll
                    for (int nn = 0; nn < 2; nn++)
                        wmma::mma_sync(sacc[mm][nn], af[mm], bf[nn], sacc[mm][nn]);
            }
#pragma unroll
            for (int mm = 0; mm < 2; mm++)
#pragma unroll
                for (int nn = 0; nn < 2; nn++)
                    wmma::store_matrix_sync(&Ps[(wm * 32 + mm * 16) * AP + wn * 32 + nn * 16],
                                            sacc[mm][nn], AP, wmma::mem_row_major);
        }
        __syncthreads();

        // mask + exp + row-sum; write P back as tf32
        {
            const int q = erow;
            const int ylo = q - kofs - 256;   // y >= ylo
            const int yhi = ylo + 512;        // y <= yhi
            float* prow = &Ps[q * AP + ecoff];
            float sum = 0.f;
#pragma unroll
            for (int j = 0; j < 32; j++) {
                int y = ecoff + j;
                bool ok = (y >= ylo) && (y <= yhi);
                float p = ok ? __expf(prow[j] + fmS[y]) : 0.f;
                sum += p;
                prow[j] = wmma::__float_to_tf32(p);
            }
            lpart += sum;
        }
        __syncthreads();

        // O += P @ V for this warp's 32 rows x 32 d-cols
        if (wvalid) {
#pragma unroll
            for (int ks = 0; ks < 8; ks++) {
                wmma::fragment<wmma::matrix_a, 16, 16, 8, wmma::precision::tf32, wmma::row_major> af[2];
                wmma::fragment<wmma::matrix_b, 16, 16, 8, wmma::precision::tf32, wmma::row_major> bf[2];
#pragma unroll
                for (int mm = 0; mm < 2; mm++)
                    wmma::load_matrix_sync(af[mm], &Ps[(wm * 32 + mm * 16) * AP + ks * 8], AP);
#pragma unroll
                for (int nn = 0; nn < 2; nn++)
                    wmma::load_matrix_sync(bf[nn], &Vs[(ks * 8) * AP + wn * 32 + nn * 16], AP);
#pragma unroll
                for (int mm = 0; mm < 2; mm++)
#pragma unroll
                    for (int nn = 0; nn < 2; nn++)
                        wmma::mma_sync(oacc[mm][nn], af[mm], bf[nn], oacc[mm][nn]);
            }
        }
    }

    lred[erow * 2 + (tid & 1)] = lpart;
    __syncthreads();
#pragma unroll
    for (int mm = 0; mm < 2; mm++)
#pragma unroll
        for (int nn = 0; nn < 2; nn++)
            wmma::store_matrix_sync(&Ps[(wm * 32 + mm * 16) * AP + wn * 32 + nn * 16],
                                    oacc[mm][nn], AP, wmma::mem_row_major);
    __syncthreads();

    const float l = lred[erow * 2] + lred[erow * 2 + 1];
    const float inv = 1.0f / l;
    size_t ob = base + (size_t)(chunk0 + erow) * E_ + ecoff;
#pragma unroll
    for (int c4 = 0; c4 < 8; c4++) {
        float* p = &Ps[erow * AP + ecoff + c4 * 4];
        float4 v = make_float4(p[0] * inv, p[1] * inv, p[2] * inv, p[3] * inv);
        *(float4*)(out + ob + c4 * 4) = v;
    }
}

// ---------------------------------------------------------------------------
extern "C" void kernel_launch(void* const* d_in, const int* in_sizes, int n_in,
                              void* d_out, int out_size) {
    const float* hs = (const float*)d_in[0];
    const int*   am = (const int*)d_in[1];
    const float* qw = (const float*)d_in[2];
    const float* qb = (const float*)d_in[3];
    const float* kw = (const float*)d_in[4];
    const float* kb = (const float*)d_in[5];
    const float* vw = (const float*)d_in[6];
    const float* vb = (const float*)d_in[7];
    float* out = (float*)d_out;

    cvt_x<<<(NTOK * KAUG + 255) / 256, 256>>>(hs);
    cvt_w<<<(E_ * KAUG + 255) / 256, 256>>>(qw, qb, 0.125f, 0);
    cvt_w<<<(E_ * KAUG + 255) / 256, 256>>>(kw, kb, 1.0f, 1);
    cvt_w<<<(E_ * KAUG + 255) / 256, 256>>>(vw, vb, 1.0f, 2);

    dim3 gg(E_ / 128, NTOK / 128, 3);
    gemm_qkv<<<gg, 256>>>();

    cudaFuncSetAttribute(attn_wmma, cudaFuncAttributeMaxDynamicSharedMemorySize, ATTN_SMEM);
    dim3 ga(S_ / 128, H_, B_);
    attn_wmma<<<ga, 256, ATTN_SMEM>>>(am, out);
}

// round 5
// speedup vs baseline: 1.9735x; 1.9735x over previous
#include <cuda_runtime.h>
#include <cuda_fp16.h>
#include <mma.h>
#include <cstdint>

using namespace nvcuda;

#define B_ 2
#define S_ 4096
#define E_ 1024
#define H_ 16
#define D_ 64
#define NTOK (B_*S_)
#define NELEM (NTOK*E_)
#define KAUG 1056   // 1024 + 32 (bias row + zero pad) = 33 tiles of BK=32

__device__ __half g_q[NELEM];
__device__ __half g_k[NELEM];
__device__ __half g_v[NELEM];
__device__ __half g_xh[NTOK * KAUG];       // fp16 X, augmented
__device__ __half g_wh[3 * E_ * KAUG];     // fp16 W (scaled), bias folded

__device__ __forceinline__ void cp16(unsigned int dst, const void* src) {
    asm volatile("cp.async.cg.shared.global [%0], [%1], 16;" :: "r"(dst), "l"(src));
}
__device__ __forceinline__ unsigned int sptr(const void* p) {
    return (unsigned int)__cvta_generic_to_shared(p);
}

// ---------------------------------------------------------------------------
// One-time conversions fp32 -> fp16 with K-augmentation (4 elems / thread).
// ---------------------------------------------------------------------------
__global__ void __launch_bounds__(256) cvt_x(const float* __restrict__ X) {
    int idx4 = blockIdx.x * 256 + threadIdx.x;
    if (idx4 >= NTOK * (KAUG / 4)) return;
    int row = idx4 / (KAUG / 4);
    int c = (idx4 - row * (KAUG / 4)) * 4;
    __half2 h0, h1;
    if (c < 1024) {
        float4 v = *(const float4*)(X + (size_t)row * 1024 + c);
        h0 = __floats2half2_rn(v.x, v.y);
        h1 = __floats2half2_rn(v.z, v.w);
    } else {
        h0 = __floats2half2_rn(c == 1024 ? 1.0f : 0.0f, 0.0f);
        h1 = __floats2half2_rn(0.0f, 0.0f);
    }
    *(__half2*)(g_xh + (size_t)row * KAUG + c) = h0;
    *(__half2*)(g_xh + (size_t)row * KAUG + c + 2) = h1;
}

__global__ void __launch_bounds__(256) cvt_w(const float* __restrict__ w,
                                             const float* __restrict__ b,
                                             float scale, int which) {
    int idx4 = blockIdx.x * 256 + threadIdx.x;
    if (idx4 >= E_ * (KAUG / 4)) return;
    int n = idx4 / (KAUG / 4);
    int c = (idx4 - n * (KAUG / 4)) * 4;
    __half2 h0, h1;
    if (c < 1024) {
        float4 v = *(const float4*)(w + (size_t)n * 1024 + c);
        h0 = __floats2half2_rn(v.x * scale, v.y * scale);
        h1 = __floats2half2_rn(v.z * scale, v.w * scale);
    } else {
        h0 = __floats2half2_rn(c == 1024 ? b[n] * scale : 0.0f, 0.0f);
        h1 = __floats2half2_rn(0.0f, 0.0f);
    }
    __half* dst = g_wh + (size_t)which * E_ * KAUG + (size_t)n * KAUG + c;
    *(__half2*)dst = h0;
    *(__half2*)(dst + 2) = h1;
}

// ---------------------------------------------------------------------------
// Projection GEMM: C = Xh @ Wh^T (bias folded), fp16 in / fp32 accum / fp16 out.
// Double-buffered cp.async, BM=BN=128, BK=32, 256 threads, warps 2x4 (64x32).
// ---------------------------------------------------------------------------
#define GK 40   // smem stride in halves (32 + 8 pad)

__global__ void __launch_bounds__(256, 2) gemm_qkv() {
    __shared__ __half As[2][128][GK];
    __shared__ __half Bs[2][128][GK];

    const int which = blockIdx.z;
    const __half* wbase = g_wh + (size_t)which * E_ * KAUG;
    __half* C = (which == 0) ? g_q : ((which == 1) ? g_k : g_v);

    const int m0 = blockIdx.y * 128;
    const int n0 = blockIdx.x * 128;
    const int tid = threadIdx.x;
    const int warp = tid >> 5;
    const int lane = tid & 31;
    const int wm = warp >> 2;    // 0..1 -> 64 rows
    const int wn = warp & 3;     // 0..3 -> 32 cols

    wmma::fragment<wmma::accumulator, 16, 16, 16, float> acc[4][2];
#pragma unroll
    for (int mm = 0; mm < 4; mm++)
#pragma unroll
        for (int nn = 0; nn < 2; nn++)
            wmma::fill_fragment(acc[mm][nn], 0.0f);

    auto issue = [&](int kt, int s) {
#pragma unroll
        for (int i = 0; i < 2; i++) {
            int c = tid + i * 256;            // 512 chunks of 8 halves
            int row = c >> 2, kc = (c & 3) * 8;
            cp16(sptr(&As[s][row][kc]), g_xh + (size_t)(m0 + row) * KAUG + kt * 32 + kc);
            cp16(sptr(&Bs[s][row][kc]), wbase + (size_t)(n0 + row) * KAUG + kt * 32 + kc);
        }
        asm volatile("cp.async.commit_group;" ::);
    };

    issue(0, 0);
    for (int kt = 0; kt < 33; kt++) {
        const int s = kt & 1;
        if (kt + 1 < 33) {
            issue(kt + 1, s ^ 1);
            asm volatile("cp.async.wait_group 1;" ::);
        } else {
            asm volatile("cp.async.wait_group 0;" ::);
        }
        __syncthreads();
#pragma unroll
        for (int ks = 0; ks < 2; ks++) {
            wmma::fragment<wmma::matrix_a, 16, 16, 16, __half, wmma::row_major> af[4];
            wmma::fragment<wmma::matrix_b, 16, 16, 16, __half, wmma::col_major> bf[2];
#pragma unroll
            for (int mm = 0; mm < 4; mm++)
                wmma::load_matrix_sync(af[mm], &As[s][wm * 64 + mm * 16][ks * 16], GK);
#pragma unroll
            for (int nn = 0; nn < 2; nn++)
                wmma::load_matrix_sync(bf[nn], &Bs[s][wn * 32 + nn * 16][ks * 16], GK);
#pragma unroll
            for (int mm = 0; mm < 4; mm++)
#pragma unroll
                for (int nn = 0; nn < 2; nn++)
                    wmma::mma_sync(acc[mm][nn], af[mm], bf[nn], acc[mm][nn]);
        }
        __syncthreads();
    }

    // Epilogue: stage fp32 through smem (reuse As), emit fp16.
    float* stage = reinterpret_cast<float*>(&As[0][0][0]);   // 20480 B
    float* wbuf = stage + warp * 16 * 40;                    // 2560 B / warp
#pragma unroll
    for (int mm = 0; mm < 4; mm++) {
        wmma::store_matrix_sync(wbuf, acc[mm][0], 40, wmma::mem_row_major);
        wmma::store_matrix_sync(wbuf + 16, acc[mm][1], 40, wmma::mem_row_major);
        __syncwarp();
        const int r = lane >> 1, cb = (lane & 1) * 16;
        const float* src = wbuf + r * 40 + cb;
        __half2 h[8];
#pragma unroll
        for (int j = 0; j < 8; j++)
            h[j] = __floats2half2_rn(src[2 * j], src[2 * j + 1]);
        __half* dst = C + (size_t)(m0 + wm * 64 + mm * 16 + r) * 1024 + n0 + wn * 32 + cb;
        *(uint4*)dst = *(uint4*)&h[0];
        *(uint4*)(dst + 8) = *(uint4*)&h[4];
        __syncwarp();
    }
}

// ---------------------------------------------------------------------------
// Banded attention, fp16 WMMA. One block = 128 queries x one (b,h).
// Band = 10 key tiles of 64. No running max (scores O(1), masked -> exp
// underflows to 0); O in fp32 fragments across tiles; warps skip fully
// out-of-band corner tiles.
// ---------------------------------------------------------------------------
#define AP 72
// bytes: Psf f32 [128][72] | Qs h [128][72] | Ks,Vs h [64][72] | Pph h [128][72] | fmS | lred
#define PSF_OFF 0
#define QS_OFF  (128*AP*4)
#define KS_OFF  (QS_OFF + 128*AP*2)
#define VS_OFF  (KS_OFF + 64*AP*2)
#define PPH_OFF (VS_OFF + 64*AP*2)
#define FMS_OFF (PPH_OFF + 128*AP*2)
#define LRED_OFF (FMS_OFF + 64*4)
#define ATTN_SMEM (LRED_OFF + 256*4)

__global__ void __launch_bounds__(256, 2) attn_wmma(const int* __restrict__ am,
                                                    float* __restrict__ out) {
    extern __shared__ char smbase[];
    float* Psf = (float*)(smbase + PSF_OFF);
    __half* Qs = (__half*)(smbase + QS_OFF);
    __half* Ks = (__half*)(smbase + KS_OFF);
    __half* Vs = (__half*)(smbase + VS_OFF);
    __half* Pph = (__half*)(smbase + PPH_OFF);
    float* fmS = (float*)(smbase + FMS_OFF);
    float* lred = (float*)(smbase + LRED_OFF);

    const int chunk0 = blockIdx.x * 128;
    const int h = blockIdx.y;
    const int b = blockIdx.z;
    const int tid = threadIdx.x;
    const int warp = tid >> 5;
    const int wm = warp >> 1;        // 0..3 -> 32 query rows
    const int wn = warp & 1;         // 0..1 -> 32 key/d cols
    const int erow = tid >> 1;       // 0..127
    const int ecoff = (tid & 1) * 32;

    const size_t base = (size_t)b * S_ * E_ + h * 64;

    // Load Q tile (half): 128 rows x 8 chunks of 8 halves
#pragma unroll
    for (int r = 0; r < 4; r++) {
        int idx = tid + r * 256;
        int row = idx >> 3, c8 = (idx & 7) * 8;
        uint4 v = *(const uint4*)(g_q + base + (size_t)(chunk0 + row) * E_ + c8);
        *(uint4*)(&Qs[row * AP + c8]) = v;
    }

    wmma::fragment<wmma::accumulator, 16, 16, 16, float> oacc[2][2];
#pragma unroll
    for (int mm = 0; mm < 2; mm++)
#pragma unroll
        for (int nn = 0; nn < 2; nn++)
            wmma::fill_fragment(oacc[mm][nn], 0.0f);
    float lpart = 0.0f;

    for (int kt = 0; kt < 10; kt++) {
        const int kglob = chunk0 - 256 + kt * 64;
        if (kglob < 0 || kglob >= S_) continue;
        const int kofs = kt * 64 - 256;
        const bool wvalid = (kofs <= wm * 32 + 31 + 256) && (kofs + 63 >= wm * 32 - 256);

        __syncthreads();
#pragma unroll
        for (int r = 0; r < 2; r++) {
            int idx = tid + r * 256;
            int row = idx >> 3, c8 = (idx & 7) * 8;
            size_t off = base + (size_t)(kglob + row) * E_ + c8;
            *(uint4*)(&Ks[row * AP + c8]) = *(const uint4*)(g_k + off);
            *(uint4*)(&Vs[row * AP + c8]) = *(const uint4*)(g_v + off);
        }
        if (tid < 64)
            fmS[tid] = (am[(size_t)b * S_ + kglob + tid] != 0) ? -10000.f : 0.f;
        __syncthreads();

        // S = Q @ K^T (this warp's 32x32 region)
        if (wvalid) {
            wmma::fragment<wmma::accumulator, 16, 16, 16, float> sacc[2][2];
#pragma unroll
            for (int mm = 0; mm < 2; mm++)
#pragma unroll
                for (int nn = 0; nn < 2; nn++)
                    wmma::fill_fragment(sacc[mm][nn], 0.0f);
#pragma unroll
            for (int ks = 0; ks < 4; ks++) {
                wmma::fragment<wmma::matrix_a, 16, 16, 16, __half, wmma::row_major> af[2];
                wmma::fragment<wmma::matrix_b, 16, 16, 16, __half, wmma::col_major> bf[2];
#pragma unroll
                for (int mm = 0; mm < 2; mm++)
                    wmma::load_matrix_sync(af[mm], &Qs[(wm * 32 + mm * 16) * AP + ks * 16], AP);
#pragma unroll
                for (int nn = 0; nn < 2; nn++)
                    wmma::load_matrix_sync(bf[nn], &Ks[(wn * 32 + nn * 16) * AP + ks * 16], AP);
#pragma unroll
                for (int mm = 0; mm < 2; mm++)
#pragma unroll
                    for (int nn = 0; nn < 2; nn++)
                        wmma::mma_sync(sacc[mm][nn], af[mm], bf[nn], sacc[mm][nn]);
            }
#pragma unroll
            for (int mm = 0; mm < 2; mm++)
#pragma unroll
                for (int nn = 0; nn < 2; nn++)
                    wmma::store_matrix_sync(&Psf[(wm * 32 + mm * 16) * AP + wn * 32 + nn * 16],
                                            sacc[mm][nn], AP, wmma::mem_row_major);
        }
        __syncthreads();

        // mask + exp + row-sum; write P as fp16
        {
            const int q = erow;
            const int ylo = q - kofs - 256;
            const int yhi = ylo + 512;
            const float* prow = &Psf[q * AP + ecoff];
            __half2* pout = (__half2*)&Pph[q * AP + ecoff];
            float sum = 0.f;
#pragma unroll
            for (int j2 = 0; j2 < 16; j2++) {
                int y0 = ecoff + j2 * 2, y1 = y0 + 1;
                bool ok0 = (y0 >= ylo) && (y0 <= yhi);
                bool ok1 = (y1 >= ylo) && (y1 <= yhi);
                float p0 = ok0 ? __expf(prow[j2 * 2] + fmS[y0]) : 0.f;
                float p1 = ok1 ? __expf(prow[j2 * 2 + 1] + fmS[y1]) : 0.f;
                sum += p0 + p1;
                pout[j2] = __floats2half2_rn(p0, p1);
            }
            lpart += sum;
        }
        __syncthreads();

        // O += P @ V (warp's 32 rows x 32 d-cols)
        if (wvalid) {
#pragma unroll
            for (int ks = 0; ks < 4; ks++) {
                wmma::fragment<wmma::matrix_a, 16, 16, 16, __half, wmma::row_major> af[2];
                wmma::fragment<wmma::matrix_b, 16, 16, 16, __half, wmma::row_major> bf[2];
#pragma unroll
                for (int mm = 0; mm < 2; mm++)
                    wmma::load_matrix_sync(af[mm], &Pph[(wm * 32 + mm * 16) * AP + ks * 16], AP);
#pragma unroll
                for (int nn = 0; nn < 2; nn++)
                    wmma::load_matrix_sync(bf[nn], &Vs[(ks * 16) * AP + wn * 32 + nn * 16], AP);
#pragma unroll
                for (int mm = 0; mm < 2; mm++)
#pragma unroll
                    for (int nn = 0; nn < 2; nn++)
                        wmma::mma_sync(oacc[mm][nn], af[mm], bf[nn], oacc[mm][nn]);
            }
        }
    }

    lred[erow * 2 + (tid & 1)] = lpart;
    __syncthreads();
#pragma unroll
    for (int mm = 0; mm < 2; mm++)
#pragma unroll
        for (int nn = 0; nn < 2; nn++)
            wmma::store_matrix_sync(&Psf[(wm * 32 + mm * 16) * AP + wn * 32 + nn * 16],
                                    oacc[mm][nn], AP, wmma::mem_row_major);
    __syncthreads();

    const float l = lred[erow * 2] + lred[erow * 2 + 1];
    const float inv = 1.0f / l;
    size_t ob = base + (size_t)(chunk0 + erow) * E_ + ecoff;
#pragma unroll
    for (int c4 = 0; c4 < 8; c4++) {
        float* p = &Psf[erow * AP + ecoff + c4 * 4];
        float4 v = make_float4(p[0] * inv, p[1] * inv, p[2] * inv, p[3] * inv);
        *(float4*)(out + ob + c4 * 4) = v;
    }
}

// ---------------------------------------------------------------------------
extern "C" void kernel_launch(void* const* d_in, const int* in_sizes, int n_in,
                              void* d_out, int out_size) {
    const float* hs = (const float*)d_in[0];
    const int*   am = (const int*)d_in[1];
    const float* qw = (const float*)d_in[2];
    const float* qb = (const float*)d_in[3];
    const float* kw = (const float*)d_in[4];
    const float* kb = (const float*)d_in[5];
    const float* vw = (const float*)d_in[6];
    const float* vb = (const float*)d_in[7];
    float* out = (float*)d_out;

    cvt_x<<<(NTOK * (KAUG / 4) + 255) / 256, 256>>>(hs);
    cvt_w<<<(E_ * (KAUG / 4) + 255) / 256, 256>>>(qw, qb, 0.125f, 0);
    cvt_w<<<(E_ * (KAUG / 4) + 255) / 256, 256>>>(kw, kb, 1.0f, 1);
    cvt_w<<<(E_ * (KAUG / 4) + 255) / 256, 256>>>(vw, vb, 1.0f, 2);

    dim3 gg(E_ / 128, NTOK / 128, 3);
    gemm_qkv<<<gg, 256>>>();

    cudaFuncSetAttribute(attn_wmma, cudaFuncAttributeMaxDynamicSharedMemorySize, ATTN_SMEM);
    dim3 ga(S_ / 128, H_, B_);
    attn_wmma<<<ga, 256, ATTN_SMEM>>>(am, out);
}

// round 7
// speedup vs baseline: 2.1119x; 1.0701x over previous
#include <cuda_runtime.h>
#include <cuda_fp16.h>
#include <mma.h>
#include <cstdint>

using namespace nvcuda;

#define B_ 2
#define S_ 4096
#define E_ 1024
#define H_ 16
#define D_ 64
#define NTOK (B_*S_)
#define NELEM (NTOK*E_)
#define KAUG 1056   // 1024 + 32 (bias row + zero pad) = 33 tiles of BK=32
#define LOG2E 1.4426950408889634f

__device__ __half g_q[NELEM];
__device__ __half g_k[NELEM];
__device__ __half g_v[NELEM];
__device__ __half g_xh[NTOK * KAUG];       // fp16 X, augmented
__device__ __half g_wh[3 * E_ * KAUG];     // fp16 W (scaled), bias folded

__device__ __forceinline__ void cp16(unsigned int dst, const void* src) {
    asm volatile("cp.async.cg.shared.global [%0], [%1], 16;" :: "r"(dst), "l"(src));
}
__device__ __forceinline__ unsigned int sptr(const void* p) {
    return (unsigned int)__cvta_generic_to_shared(p);
}
__device__ __forceinline__ __half2 hexp2_x2(__half2 x) {
    unsigned int r, xi = *(unsigned int*)&x;
    asm("ex2.approx.f16x2 %0, %1;" : "=r"(r) : "r"(xi));
    return *(__half2*)&r;
}

// ---------------------------------------------------------------------------
// One-time conversions fp32 -> fp16 with K-augmentation (8 elems / thread).
// ---------------------------------------------------------------------------
__global__ void __launch_bounds__(256) cvt_x(const float* __restrict__ X) {
    int idx8 = blockIdx.x * 256 + threadIdx.x;
    if (idx8 >= NTOK * (KAUG / 8)) return;
    int row = idx8 / (KAUG / 8);
    int c = (idx8 - row * (KAUG / 8)) * 8;
    __half2 h[4];
    if (c < 1024) {
        const float4* src = (const float4*)(X + (size_t)row * 1024 + c);
        float4 v0 = src[0], v1 = src[1];
        h[0] = __floats2half2_rn(v0.x, v0.y);
        h[1] = __floats2half2_rn(v0.z, v0.w);
        h[2] = __floats2half2_rn(v1.x, v1.y);
        h[3] = __floats2half2_rn(v1.z, v1.w);
    } else {
        h[0] = __floats2half2_rn(1.0f, 0.0f);   // bias row
        h[1] = h[2] = h[3] = __floats2half2_rn(0.0f, 0.0f);
    }
    *(uint4*)(g_xh + (size_t)row * KAUG + c) = *(uint4*)h;
}

__global__ void __launch_bounds__(256) cvt_w(const float* __restrict__ qw, const float* __restrict__ qb,
                                             const float* __restrict__ kw, const float* __restrict__ kb,
                                             const float* __restrict__ vw, const float* __restrict__ vb) {
    const int which = blockIdx.y;
    const float* w = (which == 0) ? qw : ((which == 1) ? kw : vw);
    const float* b = (which == 0) ? qb : ((which == 1) ? kb : vb);
    // Q: fold 1/sqrt(D) AND log2(e) so attention scores land in log2 domain.
    const float scale = (which == 0) ? 0.125f * LOG2E : 1.0f;

    int idx8 = blockIdx.x * 256 + threadIdx.x;
    if (idx8 >= E_ * (KAUG / 8)) return;
    int n = idx8 / (KAUG / 8);
    int c = (idx8 - n * (KAUG / 8)) * 8;
    __half2 h[4];
    if (c < 1024) {
        const float4* src = (const float4*)(w + (size_t)n * 1024 + c);
        float4 v0 = src[0], v1 = src[1];
        h[0] = __floats2half2_rn(v0.x * scale, v0.y * scale);
        h[1] = __floats2half2_rn(v0.z * scale, v0.w * scale);
        h[2] = __floats2half2_rn(v1.x * scale, v1.y * scale);
        h[3] = __floats2half2_rn(v1.z * scale, v1.w * scale);
    } else {
        h[0] = __floats2half2_rn(b[n] * scale, 0.0f);
        h[1] = h[2] = h[3] = __floats2half2_rn(0.0f, 0.0f);
    }
    *(uint4*)(g_wh + (size_t)which * E_ * KAUG + (size_t)n * KAUG + c) = *(uint4*)h;
}

// ---------------------------------------------------------------------------
// Projection GEMM: C = Xh @ Wh^T (bias folded), fp16 in / fp32 accum / fp16 out.
// 3-stage cp.async ring, BM=BN=128, BK=32, 256 threads, warps 2x4 (64x32).
// ---------------------------------------------------------------------------
#define GK 40
#define NSTG 3

__global__ void __launch_bounds__(256, 2) gemm_qkv() {
    __shared__ __half As[NSTG][128][GK];
    __shared__ __half Bs[NSTG][128][GK];

    const int which = blockIdx.z;
    const __half* wbase = g_wh + (size_t)which * E_ * KAUG;
    __half* C = (which == 0) ? g_q : ((which == 1) ? g_k : g_v);

    const int m0 = blockIdx.y * 128;
    const int n0 = blockIdx.x * 128;
    const int tid = threadIdx.x;
    const int warp = tid >> 5;
    const int lane = tid & 31;
    const int wm = warp >> 2;
    const int wn = warp & 3;

    wmma::fragment<wmma::accumulator, 16, 16, 16, float> acc[4][2];
#pragma unroll
    for (int mm = 0; mm < 4; mm++)
#pragma unroll
        for (int nn = 0; nn < 2; nn++)
            wmma::fill_fragment(acc[mm][nn], 0.0f);

    auto issue = [&](int kt, int s) {
#pragma unroll
        for (int i = 0; i < 2; i++) {
            int c = tid + i * 256;
            int row = c >> 2, kc = (c & 3) * 8;
            cp16(sptr(&As[s][row][kc]), g_xh + (size_t)(m0 + row) * KAUG + kt * 32 + kc);
            cp16(sptr(&Bs[s][row][kc]), wbase + (size_t)(n0 + row) * KAUG + kt * 32 + kc);
        }
        asm volatile("cp.async.commit_group;" ::);
    };

    issue(0, 0);
    issue(1, 1);
    for (int kt = 0; kt < 33; kt++) {
        const int s = kt % NSTG;
        const int nx = kt + 2;
        if (nx < 33) {
            issue(nx, nx % NSTG);
            asm volatile("cp.async.wait_group 2;" ::);
        } else if (kt + 1 < 33) {
            asm volatile("cp.async.wait_group 1;" ::);
        } else {
            asm volatile("cp.async.wait_group 0;" ::);
        }
        __syncthreads();
#pragma unroll
        for (int ks = 0; ks < 2; ks++) {
            wmma::fragment<wmma::matrix_a, 16, 16, 16, __half, wmma::row_major> af[4];
            wmma::fragment<wmma::matrix_b, 16, 16, 16, __half, wmma::col_major> bf[2];
#pragma unroll
            for (int mm = 0; mm < 4; mm++)
                wmma::load_matrix_sync(af[mm], &As[s][wm * 64 + mm * 16][ks * 16], GK);
#pragma unroll
            for (int nn = 0; nn < 2; nn++)
                wmma::load_matrix_sync(bf[nn], &Bs[s][wn * 32 + nn * 16][ks * 16], GK);
#pragma unroll
            for (int mm = 0; mm < 4; mm++)
#pragma unroll
                for (int nn = 0; nn < 2; nn++)
                    wmma::mma_sync(acc[mm][nn], af[mm], bf[nn], acc[mm][nn]);
        }
        __syncthreads();
    }

    // Epilogue: stage fp32 through smem, emit fp16.
    float* stage = reinterpret_cast<float*>(&As[0][0][0]);
    float* wbuf = stage + warp * 16 * 40;
#pragma unroll
    for (int mm = 0; mm < 4; mm++) {
        wmma::store_matrix_sync(wbuf, acc[mm][0], 40, wmma::mem_row_major);
        wmma::store_matrix_sync(wbuf + 16, acc[mm][1], 40, wmma::mem_row_major);
        __syncwarp();
        const int r = lane >> 1, cb = (lane & 1) * 16;
        const float* src = wbuf + r * 40 + cb;
        __half2 h[8];
#pragma unroll
        for (int j = 0; j < 8; j++)
            h[j] = __floats2half2_rn(src[2 * j], src[2 * j + 1]);
        __half* dst = C + (size_t)(m0 + wm * 64 + mm * 16 + r) * 1024 + n0 + wn * 32 + cb;
        *(uint4*)dst = *(uint4*)&h[0];
        *(uint4*)(dst + 8) = *(uint4*)&h[4];
        __syncwarp();
    }
}

// ---------------------------------------------------------------------------
// Banded attention, fp16 WMMA. One block = 128 queries x one (b,h).
// Scores arrive in log2 domain (log2e folded into Q); softmax weights via
// ex2.approx.f16x2 (2 exps per MUFU op). No running max needed.
// ---------------------------------------------------------------------------
#define AP 72
#define PSF_OFF 0
#define QS_OFF  (128*AP*4)
#define KS_OFF  (QS_OFF + 128*AP*2)
#define VS_OFF  (KS_OFF + 64*AP*2)
#define PPH_OFF (VS_OFF + 64*AP*2)
#define FMS_OFF (PPH_OFF + 128*AP*2)
#define LRED_OFF (FMS_OFF + 64*4)
#define ATTN_SMEM (LRED_OFF + 256*4)

__global__ void __launch_bounds__(256, 2) attn_wmma(const int* __restrict__ am,
                                                    float* __restrict__ out) {
    extern __shared__ char smbase[];
    float* Psf = (float*)(smbase + PSF_OFF);
    __half* Qs = (__half*)(smbase + QS_OFF);
    __half* Ks = (__half*)(smbase + KS_OFF);
    __half* Vs = (__half*)(smbase + VS_OFF);
    __half* Pph = (__half*)(smbase + PPH_OFF);
    float* fml = (float*)(smbase + FMS_OFF);    // additive mask, log2 domain
    float* lred = (float*)(smbase + LRED_OFF);

    const int chunk0 = blockIdx.x * 128;
    const int h = blockIdx.y;
    const int b = blockIdx.z;
    const int tid = threadIdx.x;
    const int warp = tid >> 5;
    const int wm = warp >> 1;
    const int wn = warp & 1;
    const int erow = tid >> 1;
    const int ecoff = (tid & 1) * 32;

    const size_t base = (size_t)b * S_ * E_ + h * 64;

#pragma unroll
    for (int r = 0; r < 4; r++) {
        int idx = tid + r * 256;
        int row = idx >> 3, c8 = (idx & 7) * 8;
        uint4 v = *(const uint4*)(g_q + base + (size_t)(chunk0 + row) * E_ + c8);
        *(uint4*)(&Qs[row * AP + c8]) = v;
    }

    wmma::fragment<wmma::accumulator, 16, 16, 16, float> oacc[2][2];
#pragma unroll
    for (int mm = 0; mm < 2; mm++)
#pragma unroll
        for (int nn = 0; nn < 2; nn++)
            wmma::fill_fragment(oacc[mm][nn], 0.0f);
    float lpart = 0.0f;

    for (int kt = 0; kt < 10; kt++) {
        const int kglob = chunk0 - 256 + kt * 64;
        if (kglob < 0 || kglob >= S_) continue;
        const int kofs = kt * 64 - 256;
        const bool wvalid = (kofs <= wm * 32 + 31 + 256) && (kofs + 63 >= wm * 32 - 256);

        __syncthreads();
#pragma unroll
        for (int r = 0; r < 2; r++) {
            int idx = tid + r * 256;
            int row = idx >> 3, c8 = (idx & 7) * 8;
            size_t off = base + (size_t)(kglob + row) * E_ + c8;
            *(uint4*)(&Ks[row * AP + c8]) = *(const uint4*)(g_k + off);
            *(uint4*)(&Vs[row * AP + c8]) = *(const uint4*)(g_v + off);
        }
        if (tid < 64)
            fml[tid] = (am[(size_t)b * S_ + kglob + tid] != 0) ? (-10000.f * LOG2E) : 0.f;
        __syncthreads();

        if (wvalid) {
            wmma::fragment<wmma::accumulator, 16, 16, 16, float> sacc[2][2];
#pragma unroll
            for (int mm = 0; mm < 2; mm++)
#pragma unroll
                for (int nn = 0; nn < 2; nn++)
                    wmma::fill_fragment(sacc[mm][nn], 0.0f);
#pragma unroll
            for (int ks = 0; ks < 4; ks++) {
                wmma::fragment<wmma::matrix_a, 16, 16, 16, __half, wmma::row_major> af[2];
                wmma::fragment<wmma::matrix_b, 16, 16, 16, __half, wmma::col_major> bf[2];
#pragma unroll
                for (int mm = 0; mm < 2; mm++)
                    wmma::load_matrix_sync(af[mm], &Qs[(wm * 32 + mm * 16) * AP + ks * 16], AP);
#pragma unroll
                for (int nn = 0; nn < 2; nn++)
                    wmma::load_matrix_sync(bf[nn], &Ks[(wn * 32 + nn * 16) * AP + ks * 16], AP);
#pragma unroll
                for (int mm = 0; mm < 2; mm++)
#pragma unroll
                    for (int nn = 0; nn < 2; nn++)
                        wmma::mma_sync(sacc[mm][nn], af[mm], bf[nn], sacc[mm][nn]);
            }
#pragma unroll
            for (int mm = 0; mm < 2; mm++)
#pragma unroll
                for (int nn = 0; nn < 2; nn++)
                    wmma::store_matrix_sync(&Psf[(wm * 32 + mm * 16) * AP + wn * 32 + nn * 16],
                                            sacc[mm][nn], AP, wmma::mem_row_major);
        }
        __syncthreads();

        // mask + 2^s + row-sum; P written as fp16 (2 exps per MUFU via f16x2)
        {
            const int q = erow;
            const int ylo = q - kofs - 256;
            const int yhi = ylo + 512;
            const float* prow = &Psf[q * AP + ecoff];
            __half2* pout = (__half2*)&Pph[q * AP + ecoff];
            float sum = 0.f;
#pragma unroll
            for (int j2 = 0; j2 < 16; j2++) {
                int y0 = ecoff + j2 * 2, y1 = y0 + 1;
                bool ok0 = (y0 >= ylo) && (y0 <= yhi);
                bool ok1 = (y1 >= ylo) && (y1 <= yhi);
                float t0 = ok0 ? (prow[j2 * 2]     + fml[y0]) : -1e30f;
                float t1 = ok1 ? (prow[j2 * 2 + 1] + fml[y1]) : -1e30f;
                __half2 p = hexp2_x2(__floats2half2_rn(t0, t1));
                pout[j2] = p;
                float2 f = __half22float2(p);
                sum += f.x + f.y;
            }
            lpart += sum;
        }
        __syncthreads();

        if (wvalid) {
#pragma unroll
            for (int ks = 0; ks < 4; ks++) {
                wmma::fragment<wmma::matrix_a, 16, 16, 16, __half, wmma::row_major> af[2];
                wmma::fragment<wmma::matrix_b, 16, 16, 16, __half, wmma::row_major> bf[2];
#pragma unroll
                for (int mm = 0; mm < 2; mm++)
                    wmma::load_matrix_sync(af[mm], &Pph[(wm * 32 + mm * 16) * AP + ks * 16], AP);
#pragma unroll
                for (int nn = 0; nn < 2; nn++)
                    wmma::load_matrix_sync(bf[nn], &Vs[(ks * 16) * AP + wn * 32 + nn * 16], AP);
#pragma unroll
                for (int mm = 0; mm < 2; mm++)
#pragma unroll
                    for (int nn = 0; nn < 2; nn++)
                        wmma::mma_sync(oacc[mm][nn], af[mm], bf[nn], oacc[mm][nn]);
            }
        }
    }

    lred[erow * 2 + (tid & 1)] = lpart;
    __syncthreads();
#pragma unroll
    for (int mm = 0; mm < 2; mm++)
#pragma unroll
        for (int nn = 0; nn < 2; nn++)
            wmma::store_matrix_sync(&Psf[(wm * 32 + mm * 16) * AP + wn * 32 + nn * 16],
                                    oacc[mm][nn], AP, wmma::mem_row_major);
    __syncthreads();

    const float l = lred[erow * 2] + lred[erow * 2 + 1];
    const float inv = 1.0f / l;
    size_t ob = base + (size_t)(chunk0 + erow) * E_ + ecoff;
#pragma unroll
    for (int c4 = 0; c4 < 8; c4++) {
        float* p = &Psf[erow * AP + ecoff + c4 * 4];
        float4 v = make_float4(p[0] * inv, p[1] * inv, p[2] * inv, p[3] * inv);
        *(float4*)(out + ob + c4 * 4) = v;
    }
}

// ---------------------------------------------------------------------------
extern "C" void kernel_launch(void* const* d_in, const int* in_sizes, int n_in,
                              void* d_out, int out_size) {
    const float* hs = (const float*)d_in[0];
    const int*   am = (const int*)d_in[1];
    const float* qw = (const float*)d_in[2];
    const float* qb = (const float*)d_in[3];
    const float* kw = (const float*)d_in[4];
    const float* kb = (const float*)d_in[5];
    const float* vw = (const float*)d_in[6];
    const float* vb = (const float*)d_in[7];
    float* out = (float*)d_out;

    cvt_x<<<(NTOK * (KAUG / 8) + 255) / 256, 256>>>(hs);
    dim3 gw((E_ * (KAUG / 8) + 255) / 256, 3);
    cvt_w<<<gw, 256>>>(qw, qb, kw, kb, vw, vb);

    dim3 gg(E_ / 128, NTOK / 128, 3);
    gemm_qkv<<<gg, 256>>>();

    cudaFuncSetAttribute(attn_wmma, cudaFuncAttributeMaxDynamicSharedMemorySize, ATTN_SMEM);
    dim3 ga(S_ / 128, H_, B_);
    attn_wmma<<<ga, 256, ATTN_SMEM>>>(am, out);
}

// round 9
// speedup vs baseline: 4.6424x; 2.1982x over previous
#include <cuda_runtime.h>
#include <cuda_fp16.h>
#include <mma.h>
#include <cstdint>

using namespace nvcuda;

#define B_ 2
#define S_ 4096
#define E_ 1024
#define H_ 16
#define D_ 64
#define NTOK (B_*S_)
#define NELEM (NTOK*E_)
#define KAUG 1056   // 1024 + 32 (bias row + zero pad) = 33 tiles of BK=32
#define LOG2E 1.4426950408889634f

__device__ __half g_q[NELEM];
__device__ __half g_k[NELEM];
__device__ __half g_v[NELEM];
__device__ __half g_xh[NTOK * KAUG];       // fp16 X, augmented
__device__ __half g_wh[3 * E_ * KAUG];     // fp16 W (scaled), bias folded

__device__ __forceinline__ void cp16(unsigned int dst, const void* src) {
    asm volatile("cp.async.cg.shared.global [%0], [%1], 16;" :: "r"(dst), "l"(src));
}
__device__ __forceinline__ unsigned int sptr(const void* p) {
    return (unsigned int)__cvta_generic_to_shared(p);
}
// exp2 of two packed fp16 values via one MUFU op; returns raw b32
__device__ __forceinline__ unsigned hexp2pk(float a, float b) {
    __half2 hv = __floats2half2_rn(a, b);
    unsigned r;
    asm("ex2.approx.f16x2 %0, %1;" : "=r"(r) : "r"(*(unsigned*)&hv));
    return r;
}
__device__ __forceinline__ void mma16816(float* d, const unsigned* a, const unsigned* b) {
    asm volatile("mma.sync.aligned.m16n8k16.row.col.f32.f16.f16.f32 "
                 "{%0,%1,%2,%3}, {%4,%5,%6,%7}, {%8,%9}, {%0,%1,%2,%3};"
                 : "+f"(d[0]), "+f"(d[1]), "+f"(d[2]), "+f"(d[3])
                 : "r"(a[0]), "r"(a[1]), "r"(a[2]), "r"(a[3]), "r"(b[0]), "r"(b[1]));
}
__device__ __forceinline__ void ldsm4(unsigned* r, unsigned addr) {
    asm volatile("ldmatrix.sync.aligned.m8n8.x4.shared.b16 {%0,%1,%2,%3}, [%4];"
                 : "=r"(r[0]), "=r"(r[1]), "=r"(r[2]), "=r"(r[3]) : "r"(addr));
}
__device__ __forceinline__ void ldsm4t(unsigned* r, unsigned addr) {
    asm volatile("ldmatrix.sync.aligned.m8n8.x4.trans.shared.b16 {%0,%1,%2,%3}, [%4];"
                 : "=r"(r[0]), "=r"(r[1]), "=r"(r[2]), "=r"(r[3]) : "r"(addr));
}

// ---------------------------------------------------------------------------
// One-time conversions fp32 -> fp16 with K-augmentation (8 elems / thread).
// ---------------------------------------------------------------------------
__global__ void __launch_bounds__(256) cvt_x(const float* __restrict__ X) {
    int idx8 = blockIdx.x * 256 + threadIdx.x;
    if (idx8 >= NTOK * (KAUG / 8)) return;
    int row = idx8 / (KAUG / 8);
    int c = (idx8 - row * (KAUG / 8)) * 8;
    __half2 h[4];
    if (c < 1024) {
        const float4* src = (const float4*)(X + (size_t)row * 1024 + c);
        float4 v0 = src[0], v1 = src[1];
        h[0] = __floats2half2_rn(v0.x, v0.y);
        h[1] = __floats2half2_rn(v0.z, v0.w);
        h[2] = __floats2half2_rn(v1.x, v1.y);
        h[3] = __floats2half2_rn(v1.z, v1.w);
    } else {
        h[0] = __floats2half2_rn(1.0f, 0.0f);   // bias row
        h[1] = h[2] = h[3] = __floats2half2_rn(0.0f, 0.0f);
    }
    *(uint4*)(g_xh + (size_t)row * KAUG + c) = *(uint4*)h;
}

__global__ void __launch_bounds__(256) cvt_w(const float* __restrict__ qw, const float* __restrict__ qb,
                                             const float* __restrict__ kw, const float* __restrict__ kb,
                                             const float* __restrict__ vw, const float* __restrict__ vb) {
    const int which = blockIdx.y;
    const float* w = (which == 0) ? qw : ((which == 1) ? kw : vw);
    const float* b = (which == 0) ? qb : ((which == 1) ? kb : vb);
    const float scale = (which == 0) ? 0.125f * LOG2E : 1.0f;   // log2e folded into Q

    int idx8 = blockIdx.x * 256 + threadIdx.x;
    if (idx8 >= E_ * (KAUG / 8)) return;
    int n = idx8 / (KAUG / 8);
    int c = (idx8 - n * (KAUG / 8)) * 8;
    __half2 h[4];
    if (c < 1024) {
        const float4* src = (const float4*)(w + (size_t)n * 1024 + c);
        float4 v0 = src[0], v1 = src[1];
        h[0] = __floats2half2_rn(v0.x * scale, v0.y * scale);
        h[1] = __floats2half2_rn(v0.z * scale, v0.w * scale);
        h[2] = __floats2half2_rn(v1.x * scale, v1.y * scale);
        h[3] = __floats2half2_rn(v1.z * scale, v1.w * scale);
    } else {
        h[0] = __floats2half2_rn(b[n] * scale, 0.0f);
        h[1] = h[2] = h[3] = __floats2half2_rn(0.0f, 0.0f);
    }
    *(uint4*)(g_wh + (size_t)which * E_ * KAUG + (size_t)n * KAUG + c) = *(uint4*)h;
}

// ---------------------------------------------------------------------------
// Projection GEMM: fp16 in / fp32 acc / fp16 out, 3-stage cp.async ring.
// ---------------------------------------------------------------------------
#define GK 40
#define NSTG 3

__global__ void __launch_bounds__(256, 2) gemm_qkv() {
    __shared__ __half As[NSTG][128][GK];
    __shared__ __half Bs[NSTG][128][GK];

    const int which = blockIdx.z;
    const __half* wbase = g_wh + (size_t)which * E_ * KAUG;
    __half* C = (which == 0) ? g_q : ((which == 1) ? g_k : g_v);

    const int m0 = blockIdx.y * 128;
    const int n0 = blockIdx.x * 128;
    const int tid = threadIdx.x;
    const int warp = tid >> 5;
    const int lane = tid & 31;
    const int wm = warp >> 2;
    const int wn = warp & 3;

    wmma::fragment<wmma::accumulator, 16, 16, 16, float> acc[4][2];
#pragma unroll
    for (int mm = 0; mm < 4; mm++)
#pragma unroll
        for (int nn = 0; nn < 2; nn++)
            wmma::fill_fragment(acc[mm][nn], 0.0f);

    auto issue = [&](int kt, int s) {
#pragma unroll
        for (int i = 0; i < 2; i++) {
            int c = tid + i * 256;
            int row = c >> 2, kc = (c & 3) * 8;
            cp16(sptr(&As[s][row][kc]), g_xh + (size_t)(m0 + row) * KAUG + kt * 32 + kc);
            cp16(sptr(&Bs[s][row][kc]), wbase + (size_t)(n0 + row) * KAUG + kt * 32 + kc);
        }
        asm volatile("cp.async.commit_group;" ::);
    };

    issue(0, 0);
    issue(1, 1);
    for (int kt = 0; kt < 33; kt++) {
        const int s = kt % NSTG;
        const int nx = kt + 2;
        if (nx < 33) {
            issue(nx, nx % NSTG);
            asm volatile("cp.async.wait_group 2;" ::);
        } else if (kt + 1 < 33) {
            asm volatile("cp.async.wait_group 1;" ::);
        } else {
            asm volatile("cp.async.wait_group 0;" ::);
        }
        __syncthreads();
#pragma unroll
        for (int ks = 0; ks < 2; ks++) {
            wmma::fragment<wmma::matrix_a, 16, 16, 16, __half, wmma::row_major> af[4];
            wmma::fragment<wmma::matrix_b, 16, 16, 16, __half, wmma::col_major> bf[2];
#pragma unroll
            for (int mm = 0; mm < 4; mm++)
                wmma::load_matrix_sync(af[mm], &As[s][wm * 64 + mm * 16][ks * 16], GK);
#pragma unroll
            for (int nn = 0; nn < 2; nn++)
                wmma::load_matrix_sync(bf[nn], &Bs[s][wn * 32 + nn * 16][ks * 16], GK);
#pragma unroll
            for (int mm = 0; mm < 4; mm++)
#pragma unroll
                for (int nn = 0; nn < 2; nn++)
                    wmma::mma_sync(acc[mm][nn], af[mm], bf[nn], acc[mm][nn]);
        }
        __syncthreads();
    }

    float* stage = reinterpret_cast<float*>(&As[0][0][0]);
    float* wbuf = stage + warp * 16 * 40;
#pragma unroll
    for (int mm = 0; mm < 4; mm++) {
        wmma::store_matrix_sync(wbuf, acc[mm][0], 40, wmma::mem_row_major);
        wmma::store_matrix_sync(wbuf + 16, acc[mm][1], 40, wmma::mem_row_major);
        __syncwarp();
        const int r = lane >> 1, cb = (lane & 1) * 16;
        const float* src = wbuf + r * 40 + cb;
        __half2 h[8];
#pragma unroll
        for (int j = 0; j < 8; j++)
            h[j] = __floats2half2_rn(src[2 * j], src[2 * j + 1]);
        __half* dst = C + (size_t)(m0 + wm * 64 + mm * 16 + r) * 1024 + n0 + wn * 32 + cb;
        *(uint4*)dst = *(uint4*)&h[0];
        *(uint4*)(dst + 8) = *(uint4*)&h[4];
        __syncwarp();
    }
}

// ---------------------------------------------------------------------------
// Banded attention, raw mma.m16n8k16 + ldmatrix (FA2 register dataflow).
// K loaded NON-trans (B pair packs over d); V loaded trans (pair over keys).
// ---------------------------------------------------------------------------
#define AP 72
#define QS_OFF 0
#define KS_OFF (128*AP*2)
#define VS_OFF (KS_OFF + 2*64*AP*2)
#define FML_OFF (VS_OFF + 2*64*AP*2)
#define ATTN_SMEM (FML_OFF + 2*64*4)

__global__ void __launch_bounds__(256, 2) attn_mma(const int* __restrict__ am,
                                                   float* __restrict__ out) {
    extern __shared__ char smb[];
    __half* Qs = (__half*)(smb + QS_OFF);
    float* fml = (float*)(smb + FML_OFF);

    const int chunk0 = blockIdx.x * 128;
    const int h = blockIdx.y;
    const int b = blockIdx.z;
    const int tid = threadIdx.x;
    const int lane = tid & 31;
    const int warp = tid >> 5;
    const int q0 = warp * 16;
    const size_t base = (size_t)b * S_ * E_ + h * 64;

    // Stage Q tile to shared
#pragma unroll
    for (int r = 0; r < 4; r++) {
        int c = tid + r * 256;
        int row = c >> 3, off = (c & 7) * 8;
        *(uint4*)(&Qs[row * AP + off]) =
            *(const uint4*)(g_q + base + (size_t)(chunk0 + row) * E_ + off);
    }

    const int kt_start = (chunk0 >= 256) ? 0 : ((256 - chunk0) / 64);
    const int kt_end = min(10, (S_ + 192 - chunk0) / 64 + 1);

    auto issueKV = [&](int kt, int s) {
        const int kglob = chunk0 - 256 + kt * 64;
        __half* Kd = (__half*)(smb + KS_OFF + s * (64 * AP * 2));
        __half* Vd = (__half*)(smb + VS_OFF + s * (64 * AP * 2));
#pragma unroll
        for (int i = 0; i < 2; i++) {
            int c = tid + i * 256;
            int row = c >> 3, off = (c & 7) * 8;
            size_t g = base + (size_t)(kglob + row) * E_ + off;
            cp16(sptr(&Kd[row * AP + off]), g_k + g);
            cp16(sptr(&Vd[row * AP + off]), g_v + g);
        }
        asm volatile("cp.async.commit_group;" ::);
        if (tid < 64)
            fml[s * 64 + tid] =
                (am[(size_t)b * S_ + kglob + tid] != 0) ? (-10000.f * LOG2E) : 0.f;
    };

    issueKV(kt_start, 0);
    __syncthreads();   // Qs visible

    // Q fragments in registers for all tiles (A operand, 4 d-steps)
    unsigned qa[4][4];
    {
        int qrow = q0 + (lane & 7) + ((lane & 8) ? 8 : 0);
        int qc = (lane & 16) ? 8 : 0;
#pragma unroll
        for (int t = 0; t < 4; t++)
            ldsm4(qa[t], sptr(&Qs[qrow * AP + t * 16 + qc]));
    }

    float oacc[8][4];
#pragma unroll
    for (int j = 0; j < 8; j++)
#pragma unroll
        for (int e = 0; e < 4; e++) oacc[j][e] = 0.f;
    float lsum0 = 0.f, lsum1 = 0.f;
    const int col0 = (lane & 3) * 2;
    const int rq0 = chunk0 + q0 + (lane >> 2);   // global query row of elems 0,1

    for (int kt = kt_start; kt < kt_end; kt++) {
        const int s = (kt - kt_start) & 1;
        const int kglob = chunk0 - 256 + kt * 64;
        if (kt + 1 < kt_end) {
            issueKV(kt + 1, s ^ 1);
            asm volatile("cp.async.wait_group 1;" ::);
        } else {
            asm volatile("cp.async.wait_group 0;" ::);
        }
        __syncthreads();
        const __half* Ks = (const __half*)(smb + KS_OFF + s * (64 * AP * 2));
        const __half* Vs = (const __half*)(smb + VS_OFF + s * (64 * AP * 2));
        const float* fm = fml + s * 64;

#pragma unroll
        for (int sub = 0; sub < 2; sub++) {
            const int klocal = sub * 32;
            // warp-level band skip (uniform across warp)
            const int lo = kglob + klocal - (chunk0 + q0 + 15);
            const int hi = kglob + klocal + 31 - (chunk0 + q0);
            if (lo > 256 || hi < -256) continue;

            // S = Q K^T for 16 rows x 32 keys (K: NON-trans ldmatrix)
            float sacc[4][4];
#pragma unroll
            for (int j = 0; j < 4; j++)
#pragma unroll
                for (int e = 0; e < 4; e++) sacc[j][e] = 0.f;
#pragma unroll
            for (int t = 0; t < 4; t++) {
#pragma unroll
                for (int p = 0; p < 2; p++) {
                    unsigned kb[4];
                    int krow = klocal + p * 16 + ((lane & 16) ? 8 : 0) + (lane & 7);
                    int kcol = t * 16 + ((lane & 8) ? 8 : 0);
                    ldsm4(kb, sptr(&Ks[krow * AP + kcol]));
                    mma16816(sacc[2 * p], qa[t], kb);
                    mma16816(sacc[2 * p + 1], qa[t], kb + 2);
                }
            }

            // mask + exp2 + row sums, P packed directly as A fragments
            unsigned pa[2][4];
#pragma unroll
            for (int jj = 0; jj < 4; jj++) {
                const int keyg = kglob + klocal + jj * 8 + col0;
                const float f0 = fm[klocal + jj * 8 + col0];
                const float f1 = fm[klocal + jj * 8 + col0 + 1];
                const int r00 = keyg - rq0;          // rel for elem (row0, key0)
                const float t00 = (r00 >= -256 && r00 <= 256) ? sacc[jj][0] + f0 : -1e5f;
                const float t01 = (r00 + 1 >= -256 && r00 + 1 <= 256) ? sacc[jj][1] + f1 : -1e5f;
                const float t10 = (r00 - 8 >= -256 && r00 - 8 <= 256) ? sacc[jj][2] + f0 : -1e5f;
                const float t11 = (r00 - 7 >= -256 && r00 - 7 <= 256) ? sacc[jj][3] + f1 : -1e5f;
                unsigned p0 = hexp2pk(t00, t01);
                unsigned p1 = hexp2pk(t10, t11);
                float2 f0v = __half22float2(*(__half2*)&p0);
                float2 f1v = __half22float2(*(__half2*)&p1);
                lsum0 += f0v.x + f0v.y;
                lsum1 += f1v.x + f1v.y;
                pa[jj >> 1][(jj & 1) * 2 + 0] = p0;
                pa[jj >> 1][(jj & 1) * 2 + 1] = p1;
            }

            // O += P V for 16 rows x 64 d (V: trans ldmatrix)
#pragma unroll
            for (int tt = 0; tt < 2; tt++) {
                const int k0 = klocal + tt * 16;
#pragma unroll
                for (int dp = 0; dp < 4; dp++) {
                    unsigned vb[4];
                    int vrow = k0 + ((lane & 8) ? 8 : 0) + (lane & 7);
                    int vcol = dp * 16 + ((lane & 16) ? 8 : 0);
                    ldsm4t(vb, sptr(&Vs[vrow * AP + vcol]));
                    mma16816(oacc[2 * dp], pa[tt], vb);
                    mma16816(oacc[2 * dp + 1], pa[tt], vb + 2);
                }
            }
        }
        __syncthreads();   // protect stage s before it is reused two iterations later
    }

    // row-sum quad reduction (lanes l^1, l^2 share the row)
    lsum0 += __shfl_xor_sync(0xffffffffu, lsum0, 1);
    lsum0 += __shfl_xor_sync(0xffffffffu, lsum0, 2);
    lsum1 += __shfl_xor_sync(0xffffffffu, lsum1, 1);
    lsum1 += __shfl_xor_sync(0xffffffffu, lsum1, 2);
    const float inv0 = 1.0f / lsum0;
    const float inv1 = 1.0f / lsum1;

    float* o0 = out + base + (size_t)rq0 * E_;
    float* o1 = out + base + (size_t)(rq0 + 8) * E_;
#pragma unroll
    for (int j = 0; j < 8; j++) {
        float2 v0 = make_float2(oacc[j][0] * inv0, oacc[j][1] * inv0);
        float2 v1 = make_float2(oacc[j][2] * inv1, oacc[j][3] * inv1);
        *(float2*)(o0 + j * 8 + col0) = v0;
        *(float2*)(o1 + j * 8 + col0) = v1;
    }
}

// ---------------------------------------------------------------------------
extern "C" void kernel_launch(void* const* d_in, const int* in_sizes, int n_in,
                              void* d_out, int out_size) {
    const float* hs = (const float*)d_in[0];
    const int*   am = (const int*)d_in[1];
    const float* qw = (const float*)d_in[2];
    const float* qb = (const float*)d_in[3];
    const float* kw = (const float*)d_in[4];
    const float* kb = (const float*)d_in[5];
    const float* vw = (const float*)d_in[6];
    const float* vb = (const float*)d_in[7];
    float* out = (float*)d_out;

    cvt_x<<<(NTOK * (KAUG / 8) + 255) / 256, 256>>>(hs);
    dim3 gw((E_ * (KAUG / 8) + 255) / 256, 3);
    cvt_w<<<gw, 256>>>(qw, qb, kw, kb, vw, vb);

    dim3 gg(E_ / 128, NTOK / 128, 3);
    gemm_qkv<<<gg, 256>>>();

    cudaFuncSetAttribute(attn_mma, cudaFuncAttributeMaxDynamicSharedMemorySize, ATTN_SMEM);
    dim3 ga(S_ / 128, H_, B_);
    attn_mma<<<ga, 256, ATTN_SMEM>>>(am, out);
}